// round 13
// baseline (speedup 1.0000x reference)
#include <cuda_runtime.h>
#include <cuda_bf16.h>
#include <math.h>
#include <stdint.h>

#define HID  1024
#define INP  256
#define BB   64
#define TSRC 256
#define TTRG 64
#define G3   3072
#define GRID 128
#define NTH  512

typedef unsigned long long ull;

// ---------------- scratch (static device globals; no runtime allocation) ----
__device__ float g_gi [(long)TSRC * BB * G3];   // precomputed input gates
__device__ float g_ys0[(long)TSRC * BB * HID];  // enc layer-0 outputs [t][b][h]
__device__ float g_h0 [2 * BB * HID];           // decoder layer-0 hidden (ping-pong)
__device__ float g_h1 [2 * BB * HID];           // decoder layer-1 hidden (ping-pong)
__device__ float g_x  [BB * INP];               // decoder AR input
__device__ unsigned g_cnt;                      // monotonic barrier counter

__device__ __forceinline__ float sigf(float x) { return 1.0f / (1.0f + expf(-x)); }

// ---- tensor-core primitives ----
__device__ __forceinline__ uint32_t smem_u32(const void* p) {
    uint32_t a;
    asm("{ .reg .u64 t; cvta.to.shared.u64 t, %1; cvt.u32.u64 %0, t; }" : "=r"(a) : "l"(p));
    return a;
}
__device__ __forceinline__ void ldsm4(uint32_t& r0, uint32_t& r1, uint32_t& r2, uint32_t& r3,
                                      uint32_t addr) {
    asm volatile("ldmatrix.sync.aligned.m8n8.x4.shared.b16 {%0,%1,%2,%3}, [%4];"
                 : "=r"(r0), "=r"(r1), "=r"(r2), "=r"(r3) : "r"(addr));
}
__device__ __forceinline__ void mma_bf16(float* d, const uint32_t* a, const uint32_t* b) {
    asm volatile(
        "mma.sync.aligned.m16n8k16.row.col.f32.bf16.bf16.f32 "
        "{%0,%1,%2,%3}, {%4,%5,%6,%7}, {%8,%9}, {%0,%1,%2,%3};"
        : "+f"(d[0]), "+f"(d[1]), "+f"(d[2]), "+f"(d[3])
        : "r"(a[0]), "r"(a[1]), "r"(a[2]), "r"(a[3]), "r"(b[0]), "r"(b[1]));
}
__device__ __forceinline__ uint32_t pack_bf2(float x, float y) {
    __nv_bfloat162 v = __floats2bfloat162_rn(x, y);
    return *(uint32_t*)&v;
}
__device__ __forceinline__ void split_bf(float x, __nv_bfloat16& hi, __nv_bfloat16& lo) {
    hi = __float2bfloat16_rn(x);
    lo = __float2bfloat16_rn(x - __bfloat162float(hi));
}
__device__ __forceinline__ uint32_t prmt_hi(uint32_t a, uint32_t b) {
    uint32_t r;
    asm("prmt.b32 %0, %1, %2, 0x7632;" : "=r"(r) : "r"(a), "r"(b));
    return r;
}
// fast truncation split: hi = trunc-bf16(x), lo = rn-bf16(x - hi)
__device__ __forceinline__ void split4_fast(float4 v, uint2& uh, uint2& ul) {
    uint32_t ax = __float_as_uint(v.x), ay = __float_as_uint(v.y);
    uint32_t az = __float_as_uint(v.z), aw = __float_as_uint(v.w);
    uh.x = prmt_hi(ax, ay);
    uh.y = prmt_hi(az, aw);
    float lx = v.x - __uint_as_float(ax & 0xFFFF0000u);
    float ly = v.y - __uint_as_float(ay & 0xFFFF0000u);
    float lz = v.z - __uint_as_float(az & 0xFFFF0000u);
    float lw = v.w - __uint_as_float(aw & 0xFFFF0000u);
    ul.x = pack_bf2(lx, ly);
    ul.y = pack_bf2(lz, lw);
}
__device__ __forceinline__ void split1_fast(float x, __nv_bfloat16& hi, __nv_bfloat16& lo) {
    uint32_t ax = __float_as_uint(x);
    uint32_t h = ax & 0xFFFF0000u;
    uint16_t hbits = (uint16_t)(ax >> 16);
    hi = *(__nv_bfloat16*)&hbits;
    lo = __float2bfloat16_rn(x - __uint_as_float(h));
}

// ---------------------------------------------------------------------------
// Cheap grid barrier: monotonic counter, release-red arrival, acquire poll.
// ---------------------------------------------------------------------------
__device__ __forceinline__ unsigned bar_init()
{
    unsigned c0;
    asm volatile("ld.relaxed.gpu.global.u32 %0, [%1];" : "=r"(c0) : "l"(&g_cnt));
    return (c0 / (unsigned)GRID + 1u) * (unsigned)GRID;
}

__device__ __forceinline__ void grid_bar(unsigned& want)
{
    __syncthreads();
    if (threadIdx.x == 0) {
        asm volatile("red.release.gpu.global.add.u32 [%0], 1;"
                     :: "l"(&g_cnt) : "memory");
        for (;;) {
            unsigned c;
            asm volatile("ld.acquire.gpu.global.u32 %0, [%1];"
                         : "=r"(c) : "l"(&g_cnt) : "memory");
            if ((int)(c - want) >= 0) break;
            __nanosleep(32);
        }
    }
    __syncthreads();
    want += (unsigned)GRID;
}

extern __shared__ float sm[];

#define WKP 1032   // padded k-stride (bf16) for encoder persistent weights
#define HKP 136    // padded k-stride (bf16) for 128-k chunk tiles
#define HSP 68     // float stride for fc scalar tile

// fragment dump: red[kw][n(24)][b(68 pad)]
__device__ __forceinline__ void dump_frag(
    float* red, const float* c0, const float* c1, const float* c2,
    int kw, int mw, int lane)
{
    float* rp = red + kw * 1632;
    int g = lane >> 2, t4 = lane & 3;
    int r0 = mw * 16 + g;
    int n0 = 2 * t4;
    rp[n0 * 68 + r0]            = c0[0];
    rp[(n0 + 1) * 68 + r0]      = c0[1];
    rp[n0 * 68 + r0 + 8]        = c0[2];
    rp[(n0 + 1) * 68 + r0 + 8]  = c0[3];
    rp[(8 + n0) * 68 + r0]           = c1[0];
    rp[(8 + n0 + 1) * 68 + r0]       = c1[1];
    rp[(8 + n0) * 68 + r0 + 8]       = c1[2];
    rp[(8 + n0 + 1) * 68 + r0 + 8]   = c1[3];
    rp[(16 + n0) * 68 + r0]          = c2[0];
    rp[(16 + n0 + 1) * 68 + r0]      = c2[1];
    rp[(16 + n0) * 68 + r0 + 8]      = c2[2];
    rp[(16 + n0 + 1) * 68 + r0 + 8]  = c2[3];
}

// ---------------------------------------------------------------------------
// Tensor-core batched input-gate GEMM (split-bf16, fused hi/lo B-ldsm4)
// ---------------------------------------------------------------------------
#define AKP 40

__global__ void __launch_bounds__(256) tc_gemm(
    const float* __restrict__ X, long sb, long st,
    const float* __restrict__ W, const float* __restrict__ bias,
    float* __restrict__ out, int K)
{
    __shared__ __nv_bfloat16 Ahi[128 * AKP];
    __shared__ __nv_bfloat16 Alo[128 * AKP];
    __shared__ __nv_bfloat16 Bhi[64 * AKP];
    __shared__ __nv_bfloat16 Blo[64 * AKP];

    const int tid  = threadIdx.x;
    const int warp = tid >> 5;
    const int lane = tid & 31;
    const long cb  = (long)blockIdx.x * 64;
    const long rb  = (long)blockIdx.y * 128;

    const int rowA = warp * 16 + ((lane >> 3) & 1) * 8 + (lane & 7);
    const int kA   = ((lane >> 4) & 1) * 8;
    const int lm   = lane & 15;
    const int bRow = lm & 7;
    const int bK   = ((lm >> 3) & 1) * 8;
    const uint32_t AhiA = smem_u32(Ahi);
    const uint32_t AloA = smem_u32(Alo);
    // fused hi/lo B base: lanes 0-15 -> Bhi rows, lanes 16-31 -> Blo rows
    const uint32_t bBase = ((lane & 16) ? smem_u32(Blo) : smem_u32(Bhi))
                         + (uint32_t)((bRow * AKP + bK) * 2);

    float acc[8][4];
#pragma unroll
    for (int n = 0; n < 8; n++)
#pragma unroll
        for (int i = 0; i < 4; i++) acc[n][i] = 0.0f;

    for (int k0 = 0; k0 < K; k0 += 32) {
        __syncthreads();
#pragma unroll
        for (int i = 0; i < 4; i++) {
            int idx = (i << 8) + tid;
            int row = idx >> 3, q = idx & 7;
            long r = rb + row;
            long off = (r & 63) * sb + (r >> 6) * st + k0 + (q << 2);
            float4 v = *(const float4*)(X + off);
            uint2 uh, ul;
            split4_fast(v, uh, ul);
            *(uint2*)&Ahi[row * AKP + (q << 2)] = uh;
            *(uint2*)&Alo[row * AKP + (q << 2)] = ul;
        }
#pragma unroll
        for (int i = 0; i < 2; i++) {
            int idx = (i << 8) + tid;
            int row = idx >> 3, q = idx & 7;
            float4 v = *(const float4*)(W + (cb + row) * (long)K + k0 + (q << 2));
            uint2 uh, ul;
            split4_fast(v, uh, ul);
            *(uint2*)&Bhi[row * AKP + (q << 2)] = uh;
            *(uint2*)&Blo[row * AKP + (q << 2)] = ul;
        }
        __syncthreads();

#pragma unroll
        for (int s = 0; s < 2; s++) {
            int kk = s * 16;
            uint32_t ah[4], al[4];
            ldsm4(ah[0], ah[1], ah[2], ah[3],
                  AhiA + (uint32_t)((rowA * AKP + kk + kA) * 2));
            ldsm4(al[0], al[1], al[2], al[3],
                  AloA + (uint32_t)((rowA * AKP + kk + kA) * 2));
#pragma unroll
            for (int nt = 0; nt < 8; nt++) {
                uint32_t bb[4];   // bb[0..1]=hi frag, bb[2..3]=lo frag
                ldsm4(bb[0], bb[1], bb[2], bb[3],
                      bBase + (uint32_t)((nt * 8 * AKP + kk) * 2));
                mma_bf16(acc[nt], ah, bb);
                mma_bf16(acc[nt], ah, bb + 2);
                mma_bf16(acc[nt], al, bb);
            }
        }
    }

    const int g  = lane >> 2;
    const int t4 = lane & 3;
#pragma unroll
    for (int nt = 0; nt < 8; nt++) {
        long c = cb + nt * 8 + t4 * 2;
        float2 bv = *(const float2*)(bias + c);
        long r0 = rb + warp * 16 + g;
        *(float2*)(out + r0 * G3 + c) = make_float2(acc[nt][0] + bv.x, acc[nt][1] + bv.y);
        *(float2*)(out + (r0 + 8) * G3 + c) = make_float2(acc[nt][2] + bv.x, acc[nt][3] + bv.y);
    }
}

// ---------------------------------------------------------------------------
// Persistent encoder layer — fused weight ldsm4, double-buffered h tiles
// (1 sync per chunk), coalesced fp32 staging + split, cheap barrier.
// SMEM: whi/wlo 24*WKP | hb[2]{hi,lo} 64*HKP | red | gis  = 201216 B
// ---------------------------------------------------------------------------
__global__ void __launch_bounds__(NTH, 1) enc_layer_kernel(
    const float* __restrict__ gi,
    const float* __restrict__ Wh,
    const float* __restrict__ bh,
    float* __restrict__ out, long out_t, long out_b)
{
    __nv_bfloat16* whi = (__nv_bfloat16*)sm;
    __nv_bfloat16* wlo = whi + 24 * WKP;
    __nv_bfloat16* hb  = wlo + 24 * WKP;        // [buf][hi/lo][64*HKP]
    float* red = (float*)(hb + 4 * 64 * HKP);
    float* gis = red + 4 * 24 * 68;

    const int tid  = threadIdx.x;
    const int j0   = blockIdx.x << 3;
    const int warp = tid >> 5;
    const int lane = tid & 31;
    const int mw   = warp & 3;
    const int kw   = warp >> 2;
    const int eb   = tid >> 3;
    const int ej   = tid & 7;
    const int ecol = j0 + ej;

    unsigned want = bar_init();

    for (int i = 0; i < 48; i++) {
        int idx = tid + (i << 9);
        int c = idx >> 10, k = idx & 1023;
        int row = ((c >> 3) << 10) + j0 + (c & 7);
        float w = Wh[(long)row * HID + k];
        __nv_bfloat16 hi, lo;
        split_bf(w, hi, lo);
        whi[c * WKP + k] = hi;
        wlo[c * WKP + k] = lo;
    }
    const float bhr = bh[ecol];
    const float bhz = bh[HID + ecol];
    const float bhn = bh[2 * HID + ecol];

    const int rowA = mw * 16 + ((lane >> 3) & 1) * 8 + (lane & 7);
    const int kA   = ((lane >> 4) & 1) * 8;
    const int lm   = lane & 15;
    const int bOff = (lm & 7) * WKP + ((lm >> 3) & 1) * 8;
    // fused hi/lo weight base
    const uint32_t wBase = ((lane & 16) ? smem_u32(wlo) : smem_u32(whi))
                         + (uint32_t)(bOff * 2);
    uint32_t hbA[2][2];
#pragma unroll
    for (int b = 0; b < 2; b++) {
        hbA[b][0] = smem_u32(hb + (2 * b)     * 64 * HKP);
        hbA[b][1] = smem_u32(hb + (2 * b + 1) * 64 * HKP);
    }

    const int srow = tid >> 3;
    const int sq   = tid & 7;
    __syncthreads();

    for (int t = 0; t < TSRC; t++) {
        float c0[4], c1[4], c2[4];
#pragma unroll
        for (int i = 0; i < 4; i++) { c0[i] = 0.f; c1[i] = 0.f; c2[i] = 0.f; }

        const float* hprev = out + (long)(t - 1) * out_t;
        float hold = 0.0f;
        float4 rA[4];
        if (t > 0) {
            hold = hprev[(long)eb * out_b + ecol];
#pragma unroll
            for (int i = 0; i < 4; i++) {
                int k4 = sq + (i << 3);
                rA[i] = *(const float4*)(hprev + (long)srow * out_b + (k4 << 2));
            }
        }

        // stage gi tile
        {
            const float* gi_t = gi + (long)t * BB * G3;
#pragma unroll
            for (int i = 0; i < 3; i++) {
                int idx = (i << 9) + tid;
                int b = idx / 24;
                int rem = idx - b * 24;
                gis[b * 25 + rem] = gi_t[(long)b * G3 + ((rem >> 3) << 10) + j0 + (rem & 7)];
            }
        }

        if (t > 0) {
            for (int c = 0; c < 8; c++) {
                // store chunk c from regs into buf c&1
                {
                    __nv_bfloat16* dh = hb + (2 * (c & 1)) * 64 * HKP;
                    __nv_bfloat16* dl = dh + 64 * HKP;
#pragma unroll
                    for (int i = 0; i < 4; i++) {
                        int k4 = sq + (i << 3);
                        uint2 uh, ul;
                        split4_fast(rA[i], uh, ul);
                        *(uint2*)&dh[srow * HKP + (k4 << 2)] = uh;
                        *(uint2*)&dl[srow * HKP + (k4 << 2)] = ul;
                    }
                }
                __syncthreads();
                // prefetch chunk c+1
                if (c < 7) {
                    int k0n = (c + 1) << 7;
#pragma unroll
                    for (int i = 0; i < 4; i++) {
                        int k4 = sq + (i << 3);
                        rA[i] = *(const float4*)(hprev + (long)srow * out_b + k0n + (k4 << 2));
                    }
                }
                // MMA on chunk c
                const uint32_t hhiA = hbA[c & 1][0];
                const uint32_t hloA = hbA[c & 1][1];
                const int k0 = c << 7;
#pragma unroll
                for (int s = 0; s < 2; s++) {
                    int kk = kw * 32 + s * 16;
                    int kg = k0 + kk;
                    uint32_t ah[4], al[4];
                    ldsm4(ah[0], ah[1], ah[2], ah[3],
                          hhiA + (uint32_t)((rowA * HKP + kk + kA) * 2));
                    ldsm4(al[0], al[1], al[2], al[3],
                          hloA + (uint32_t)((rowA * HKP + kk + kA) * 2));
                    uint32_t bb[4];
                    ldsm4(bb[0], bb[1], bb[2], bb[3], wBase + (uint32_t)(kg * 2));
                    mma_bf16(c0, ah, bb); mma_bf16(c0, ah, bb + 2); mma_bf16(c0, al, bb);
                    ldsm4(bb[0], bb[1], bb[2], bb[3],
                          wBase + (uint32_t)((8 * WKP + kg) * 2));
                    mma_bf16(c1, ah, bb); mma_bf16(c1, ah, bb + 2); mma_bf16(c1, al, bb);
                    ldsm4(bb[0], bb[1], bb[2], bb[3],
                          wBase + (uint32_t)((16 * WKP + kg) * 2));
                    mma_bf16(c2, ah, bb); mma_bf16(c2, ah, bb + 2); mma_bf16(c2, al, bb);
                }
            }
        }
        __syncthreads();
        dump_frag(red, c0, c1, c2, kw, mw, lane);
        __syncthreads();

        float s0 = 0.f, s1 = 0.f, s2 = 0.f;
#pragma unroll
        for (int k = 0; k < 4; k++) {
            const float* rp = red + k * 1632 + eb;
            s0 += rp[(ej)      * 68];
            s1 += rp[(8 + ej)  * 68];
            s2 += rp[(16 + ej) * 68];
        }
        const float* gp = gis + eb * 25;
        float GR = gp[ej], GZ = gp[8 + ej], GN = gp[16 + ej];
        float r = sigf(GR + s0 + bhr);
        float z = sigf(GZ + s1 + bhz);
        float n = tanhf(GN + r * (s2 + bhn));
        float hn = (1.0f - z) * n + z * hold;
        out[(long)t * out_t + (long)eb * out_b + ecol] = hn;

        if (t < TSRC - 1) grid_bar(want);
    }
}

// ---------------------------------------------------------------------------
// Decoder tensor phase — fused weight ldsm4
// ---------------------------------------------------------------------------
struct TcCtx {
    __nv_bfloat16 *wshi, *wslo, *hhi, *hlo;
    uint32_t wBase, hhiA, hloA;
    int rowA, kA, kw, tid, j0;
};

__device__ __forceinline__ void tc_phase(
    const float* __restrict__ X, long xs,
    const float* __restrict__ W, int K,
    const TcCtx& cx,
    float (&c0)[4], float (&c1)[4], float (&c2)[4])
{
    const int NC = K >> 7;
    const int srow = cx.tid >> 3;
    const int sq   = cx.tid & 7;
    float4 rx[4];
    float  rw[6];
#pragma unroll
    for (int i = 0; i < 4; i++) {
        int k4 = sq + (i << 3);
        rx[i] = *(const float4*)(X + (long)srow * xs + (k4 << 2));
    }
#pragma unroll
    for (int i = 0; i < 6; i++) {
        int idx = (i << 9) + cx.tid;
        int c = idx >> 7, k = idx & 127;
        int row = ((c >> 3) << 10) + cx.j0 + (c & 7);
        rw[i] = W[(long)row * (long)K + k];
    }
    for (int ci = 0; ci < NC; ci++) {
        __syncthreads();
#pragma unroll
        for (int i = 0; i < 4; i++) {
            int k4 = sq + (i << 3);
            uint2 uh, ul;
            split4_fast(rx[i], uh, ul);
            *(uint2*)&cx.hhi[srow * HKP + (k4 << 2)] = uh;
            *(uint2*)&cx.hlo[srow * HKP + (k4 << 2)] = ul;
        }
#pragma unroll
        for (int i = 0; i < 6; i++) {
            int idx = (i << 9) + cx.tid;
            int c = idx >> 7, k = idx & 127;
            __nv_bfloat16 hi, lo;
            split1_fast(rw[i], hi, lo);
            cx.wshi[c * HKP + k] = hi;
            cx.wslo[c * HKP + k] = lo;
        }
        __syncthreads();
        if (ci + 1 < NC) {
            int k0 = (ci + 1) << 7;
#pragma unroll
            for (int i = 0; i < 4; i++) {
                int k4 = sq + (i << 3);
                rx[i] = *(const float4*)(X + (long)srow * xs + k0 + (k4 << 2));
            }
#pragma unroll
            for (int i = 0; i < 6; i++) {
                int idx = (i << 9) + cx.tid;
                int c = idx >> 7, k = idx & 127;
                int row = ((c >> 3) << 10) + cx.j0 + (c & 7);
                rw[i] = W[(long)row * (long)K + k0 + k];
            }
        }
#pragma unroll
        for (int s = 0; s < 2; s++) {
            int kk = cx.kw * 32 + s * 16;
            uint32_t ah[4], al[4];
            ldsm4(ah[0], ah[1], ah[2], ah[3],
                  cx.hhiA + (uint32_t)((cx.rowA * HKP + kk + cx.kA) * 2));
            ldsm4(al[0], al[1], al[2], al[3],
                  cx.hloA + (uint32_t)((cx.rowA * HKP + kk + cx.kA) * 2));
            uint32_t bb[4];
            ldsm4(bb[0], bb[1], bb[2], bb[3], cx.wBase + (uint32_t)(kk * 2));
            mma_bf16(c0, ah, bb); mma_bf16(c0, ah, bb + 2); mma_bf16(c0, al, bb);
            ldsm4(bb[0], bb[1], bb[2], bb[3],
                  cx.wBase + (uint32_t)((8 * HKP + kk) * 2));
            mma_bf16(c1, ah, bb); mma_bf16(c1, ah, bb + 2); mma_bf16(c1, al, bb);
            ldsm4(bb[0], bb[1], bb[2], bb[3],
                  cx.wBase + (uint32_t)((16 * HKP + kk) * 2));
            mma_bf16(c2, ah, bb); mma_bf16(c2, ah, bb + 2); mma_bf16(c2, al, bb);
        }
    }
}

#define ZFRAG(c0, c1, c2) \
    do { _Pragma("unroll") for (int i_ = 0; i_ < 4; i_++) { c0[i_]=0.f; c1[i_]=0.f; c2[i_]=0.f; } } while (0)

// ---------------------------------------------------------------------------
// Persistent decoder (fused weight ldsm4, cheap barrier)
// ---------------------------------------------------------------------------
__global__ void __launch_bounds__(NTH, 1) dec_kernel(
    const float* __restrict__ dWi0, const float* __restrict__ dWh0,
    const float* __restrict__ dbi0, const float* __restrict__ dbh0,
    const float* __restrict__ dWi1, const float* __restrict__ dWh1,
    const float* __restrict__ dbi1, const float* __restrict__ dbh1,
    const float* __restrict__ fcW,  const float* __restrict__ fcb,
    const float* __restrict__ enc0_hT,
    const float* __restrict__ enc1_hT,
    float* __restrict__ h0buf, float* __restrict__ h1buf, float* __restrict__ xbuf,
    float* __restrict__ out,
    float* __restrict__ dec_out)
{
    __nv_bfloat16* wshi = (__nv_bfloat16*)sm;
    __nv_bfloat16* wslo = wshi + 24 * HKP;
    __nv_bfloat16* hhi  = wslo + 24 * HKP;
    __nv_bfloat16* hlo  = hhi + 64 * HKP;
    float* redA = (float*)(hlo + 64 * HKP);
    float* redB = redA + 4 * 24 * 68;
    float* fcw  = (float*)sm;
    float* fch  = (float*)hhi;

    const int tid  = threadIdx.x;
    const int j0   = blockIdx.x << 3;
    const int warp = tid >> 5;
    const int lane = tid & 31;
    const int mw   = warp & 3;
    const int kw   = warp >> 2;
    const int eb   = tid >> 3;
    const int ej   = tid & 7;
    const int ecol = j0 + ej;
    const int fb   = tid >> 3;
    const int fcc  = (tid >> 2) & 1;
    const int fks  = tid & 3;
    const int fcol = (blockIdx.x << 1) + fcc;

    TcCtx cx;
    cx.wshi = wshi; cx.wslo = wslo; cx.hhi = hhi; cx.hlo = hlo;
    cx.hhiA = smem_u32(hhi);   cx.hloA = smem_u32(hlo);
    cx.rowA = mw * 16 + ((lane >> 3) & 1) * 8 + (lane & 7);
    cx.kA   = ((lane >> 4) & 1) * 8;
    {
        int lm = lane & 15;
        int bOff = (lm & 7) * HKP + ((lm >> 3) & 1) * 8;
        cx.wBase = ((lane & 16) ? smem_u32(wslo) : smem_u32(wshi))
                 + (uint32_t)(bOff * 2);
    }
    cx.kw = kw; cx.tid = tid; cx.j0 = j0;

    unsigned want = bar_init();

    const float b0ir = dbi0[ecol], b0iz = dbi0[HID + ecol], b0in = dbi0[2 * HID + ecol];
    const float b0hr = dbh0[ecol], b0hz = dbh0[HID + ecol], b0hn = dbh0[2 * HID + ecol];
    const float b1ir = dbi1[ecol], b1iz = dbi1[HID + ecol], b1in = dbi1[2 * HID + ecol];
    const float b1hr = dbh1[ecol], b1hz = dbh1[HID + ecol], b1hn = dbh1[2 * HID + ecol];
    const float fcbv = fcb[fcol];

    float c0[4], c1[4], c2[4];

    for (int t = 0; t < TTRG; t++) {
        const int w = t & 1;

        // ================= layer 0 =================
        ZFRAG(c0, c1, c2);
        if (t > 0)
            tc_phase(xbuf, INP, dWi0, INP, cx, c0, c1, c2);
        __syncthreads();
        dump_frag(redA, c0, c1, c2, kw, mw, lane);

        const float* h0p = t ? h0buf + (long)(1 - w) * BB * HID : enc0_hT;
        ZFRAG(c0, c1, c2);
        tc_phase(h0p, HID, dWh0, HID, cx, c0, c1, c2);
        __syncthreads();
        dump_frag(redB, c0, c1, c2, kw, mw, lane);
        __syncthreads();
        {
            float a0 = 0.f, a1 = 0.f, a2 = 0.f, d0 = 0.f, d1 = 0.f, d2 = 0.f;
#pragma unroll
            for (int k = 0; k < 4; k++) {
                const float* ra = redA + k * 1632 + eb;
                const float* rb = redB + k * 1632 + eb;
                a0 += ra[ej * 68];        d0 += rb[ej * 68];
                a1 += ra[(8 + ej) * 68];  d1 += rb[(8 + ej) * 68];
                a2 += ra[(16 + ej) * 68]; d2 += rb[(16 + ej) * 68];
            }
            float hold = h0p[(long)eb * HID + ecol];
            float r = sigf(a0 + b0ir + d0 + b0hr);
            float z = sigf(a1 + b0iz + d1 + b0hz);
            float n = tanhf(a2 + b0in + r * (d2 + b0hn));
            h0buf[(long)w * BB * HID + (long)eb * HID + ecol] = (1.f - z) * n + z * hold;
        }
        grid_bar(want);

        // ================= layer 1 =================
        const float* x1 = h0buf + (long)w * BB * HID;
        ZFRAG(c0, c1, c2);
        tc_phase(x1, HID, dWi1, HID, cx, c0, c1, c2);
        __syncthreads();
        dump_frag(redA, c0, c1, c2, kw, mw, lane);

        const float* h1p = t ? h1buf + (long)(1 - w) * BB * HID : enc1_hT;
        const long   h1s = t ? (long)HID : (long)TSRC * HID;
        ZFRAG(c0, c1, c2);
        tc_phase(h1p, h1s, dWh1, HID, cx, c0, c1, c2);
        __syncthreads();
        dump_frag(redB, c0, c1, c2, kw, mw, lane);
        __syncthreads();
        {
            float a0 = 0.f, a1 = 0.f, a2 = 0.f, d0 = 0.f, d1 = 0.f, d2 = 0.f;
#pragma unroll
            for (int k = 0; k < 4; k++) {
                const float* ra = redA + k * 1632 + eb;
                const float* rb = redB + k * 1632 + eb;
                a0 += ra[ej * 68];        d0 += rb[ej * 68];
                a1 += ra[(8 + ej) * 68];  d1 += rb[(8 + ej) * 68];
                a2 += ra[(16 + ej) * 68]; d2 += rb[(16 + ej) * 68];
            }
            float hold = h1p[(long)eb * h1s + ecol];
            float r = sigf(a0 + b1ir + d0 + b1hr);
            float z = sigf(a1 + b1iz + d1 + b1hz);
            float n = tanhf(a2 + b1in + r * (d2 + b1hn));
            float hn = (1.f - z) * n + z * hold;
            h1buf[(long)w * BB * HID + (long)eb * HID + ecol] = hn;
            dec_out[(long)eb * TTRG * HID + (long)t * HID + ecol] = hn;
        }
        grid_bar(want);

        // ================= fc (scalar, pipelined, overlaid SMEM) ============
        {
            const float* h1c = h1buf + (long)w * BB * HID;
            const int sb = tid >> 3;
            const int sq = tid & 7;
            __syncthreads();
#pragma unroll
            for (int i = 0; i < 4; i++) {
                int idx = (i << 9) + tid;
                int k = idx >> 1, c = idx & 1;
                fcw[idx] = fcW[(long)((blockIdx.x << 1) + c) * HID + k];
            }
            float4 rx[4];
#pragma unroll
            for (int i = 0; i < 4; i++) {
                int k4 = sq + (i << 3);
                rx[i] = *(const float4*)(h1c + (long)sb * HID + (k4 << 2));
            }
            float partial = 0.f;
            for (int ci = 0; ci < 8; ci++) {
                __syncthreads();
#pragma unroll
                for (int i = 0; i < 4; i++) {
                    int k4 = sq + (i << 3);
                    int base = (k4 << 2) * HSP + sb;
                    fch[base]           = rx[i].x;
                    fch[base + HSP]     = rx[i].y;
                    fch[base + 2 * HSP] = rx[i].z;
                    fch[base + 3 * HSP] = rx[i].w;
                }
                __syncthreads();
                if (ci + 1 < 8) {
                    int k0 = (ci + 1) << 7;
#pragma unroll
                    for (int i = 0; i < 4; i++) {
                        int k4 = sq + (i << 3);
                        rx[i] = *(const float4*)(h1c + (long)sb * HID + k0 + (k4 << 2));
                    }
                }
                int k0 = ci << 7;
#pragma unroll 8
                for (int i = 0; i < 32; i++) {
                    int kk = fks * 32 + i;
                    partial += fch[kk * HSP + fb] * fcw[(k0 + kk) * 2 + fcc];
                }
            }
            __syncthreads();
            redA[tid] = partial;
            __syncthreads();
            if (fks == 0) {
                float s = redA[tid] + redA[tid + 1] + redA[tid + 2] + redA[tid + 3] + fcbv;
                out [(long)fb * TTRG * INP + (long)t * INP + fcol] = s;
                xbuf[(long)fb * INP + fcol] = s;
            }
        }
        grid_bar(want);
    }
}

// ---------------------------------------------------------------------------
extern "C" void kernel_launch(void* const* d_in, const int* in_sizes, int n_in,
                              void* d_out, int out_size)
{
    const float* src  = (const float*)d_in[0];
    const float* eWi0 = (const float*)d_in[2];
    const float* eWh0 = (const float*)d_in[3];
    const float* ebi0 = (const float*)d_in[4];
    const float* ebh0 = (const float*)d_in[5];
    const float* eWi1 = (const float*)d_in[6];
    const float* eWh1 = (const float*)d_in[7];
    const float* ebi1 = (const float*)d_in[8];
    const float* ebh1 = (const float*)d_in[9];
    const float* dWi0 = (const float*)d_in[10];
    const float* dWh0 = (const float*)d_in[11];
    const float* dbi0 = (const float*)d_in[12];
    const float* dbh0 = (const float*)d_in[13];
    const float* dWi1 = (const float*)d_in[14];
    const float* dWh1 = (const float*)d_in[15];
    const float* dbi1 = (const float*)d_in[16];
    const float* dbh1 = (const float*)d_in[17];
    const float* fcW  = (const float*)d_in[18];
    const float* fcb  = (const float*)d_in[19];

    float* out     = (float*)d_out;                   // [64, 64, 256]
    float* enc_out = out + (long)BB * TTRG * INP;     // [64, 256, 1024]
    float* dec_out = enc_out + (long)BB * TSRC * HID; // [64, 64, 1024]

    float *gi, *ys0, *h0, *h1, *xbuf;
    cudaGetSymbolAddress((void**)&gi,   g_gi);
    cudaGetSymbolAddress((void**)&ys0,  g_ys0);
    cudaGetSymbolAddress((void**)&h0,   g_h0);
    cudaGetSymbolAddress((void**)&h1,   g_h1);
    cudaGetSymbolAddress((void**)&xbuf, g_x);

    const int ENC_SMEM = 24 * WKP * 2 * 2          // whi+wlo
                       + 4 * 64 * HKP * 2          // double-buffered hi/lo h tiles
                       + 4 * 24 * 68 * 4           // red
                       + 64 * 25 * 4;              // gis  = 201216 B
    const int DEC_SMEM = (24 * HKP * 2 + 64 * HKP * 2) * 2
                       + 2 * 4 * 24 * 68 * 4;      // 100096 B
    cudaFuncSetAttribute(enc_layer_kernel,
                         cudaFuncAttributeMaxDynamicSharedMemorySize, ENC_SMEM);
    cudaFuncSetAttribute(dec_kernel,
                         cudaFuncAttributeMaxDynamicSharedMemorySize, DEC_SMEM);

    dim3 gridTc(48, 128);

    // ---------- encoder layer 0 ----------
    tc_gemm<<<gridTc, 256>>>(src, 65536L, 256L, eWi0, ebi0, gi, 256);
    enc_layer_kernel<<<GRID, NTH, ENC_SMEM>>>(
        gi, eWh0, ebh0, ys0, (long)BB * HID, (long)HID);

    // ---------- encoder layer 1 ----------
    tc_gemm<<<gridTc, 256>>>(ys0, 1024L, 65536L, eWi1, ebi1, gi, 1024);
    enc_layer_kernel<<<GRID, NTH, ENC_SMEM>>>(
        gi, eWh1, ebh1, enc_out, (long)HID, (long)TSRC * HID);

    // ---------- decoder ----------
    dec_kernel<<<GRID, NTH, DEC_SMEM>>>(
        dWi0, dWh0, dbi0, dbh0,
        dWi1, dWh1, dbi1, dbh1,
        fcW, fcb,
        ys0 + (long)(TSRC - 1) * BB * HID,
        enc_out + (long)(TSRC - 1) * HID,
        h0, h1, xbuf,
        out, dec_out);
}

// round 14
// speedup vs baseline: 1.0790x; 1.0790x over previous
#include <cuda_runtime.h>
#include <cuda_bf16.h>
#include <math.h>
#include <stdint.h>

#define HID  1024
#define INP  256
#define BB   64
#define TSRC 256
#define TTRG 64
#define G3   3072
#define GRID 128
#define NTH  512

typedef unsigned long long ull;

// ---------------- scratch (static device globals; no runtime allocation) ----
__device__ float g_gi [(long)TSRC * BB * G3];   // precomputed input gates
__device__ float g_ys0[(long)TSRC * BB * HID];  // enc layer-0 outputs [t][b][h]
__device__ float g_h0 [2 * BB * HID];           // decoder layer-0 hidden (ping-pong)
__device__ float g_h1 [2 * BB * HID];           // decoder layer-1 hidden (ping-pong)
__device__ float g_x  [BB * INP];               // decoder AR input
__device__ unsigned g_cnt;                      // monotonic barrier counter

__device__ __forceinline__ float sigf(float x) { return 1.0f / (1.0f + expf(-x)); }

// ---- tensor-core primitives ----
__device__ __forceinline__ uint32_t smem_u32(const void* p) {
    uint32_t a;
    asm("{ .reg .u64 t; cvta.to.shared.u64 t, %1; cvt.u32.u64 %0, t; }" : "=r"(a) : "l"(p));
    return a;
}
__device__ __forceinline__ void ldsm4(uint32_t& r0, uint32_t& r1, uint32_t& r2, uint32_t& r3,
                                      uint32_t addr) {
    asm volatile("ldmatrix.sync.aligned.m8n8.x4.shared.b16 {%0,%1,%2,%3}, [%4];"
                 : "=r"(r0), "=r"(r1), "=r"(r2), "=r"(r3) : "r"(addr));
}
__device__ __forceinline__ void ldsm2(uint32_t& r0, uint32_t& r1, uint32_t addr) {
    asm volatile("ldmatrix.sync.aligned.m8n8.x2.shared.b16 {%0,%1}, [%2];"
                 : "=r"(r0), "=r"(r1) : "r"(addr));
}
__device__ __forceinline__ void mma_bf16(float* d, const uint32_t* a, const uint32_t* b) {
    asm volatile(
        "mma.sync.aligned.m16n8k16.row.col.f32.bf16.bf16.f32 "
        "{%0,%1,%2,%3}, {%4,%5,%6,%7}, {%8,%9}, {%0,%1,%2,%3};"
        : "+f"(d[0]), "+f"(d[1]), "+f"(d[2]), "+f"(d[3])
        : "r"(a[0]), "r"(a[1]), "r"(a[2]), "r"(a[3]), "r"(b[0]), "r"(b[1]));
}
__device__ __forceinline__ uint32_t pack_bf2(float x, float y) {
    __nv_bfloat162 v = __floats2bfloat162_rn(x, y);
    return *(uint32_t*)&v;
}
__device__ __forceinline__ void split_bf(float x, __nv_bfloat16& hi, __nv_bfloat16& lo) {
    hi = __float2bfloat16_rn(x);
    lo = __float2bfloat16_rn(x - __bfloat162float(hi));
}
__device__ __forceinline__ uint32_t prmt_hi(uint32_t a, uint32_t b) {
    uint32_t r;
    asm("prmt.b32 %0, %1, %2, 0x7632;" : "=r"(r) : "r"(a), "r"(b));
    return r;
}
// fast truncation split: hi = trunc-bf16(x), lo = rn-bf16(x - hi)
__device__ __forceinline__ void split4_fast(float4 v, uint2& uh, uint2& ul) {
    uint32_t ax = __float_as_uint(v.x), ay = __float_as_uint(v.y);
    uint32_t az = __float_as_uint(v.z), aw = __float_as_uint(v.w);
    uh.x = prmt_hi(ax, ay);
    uh.y = prmt_hi(az, aw);
    float lx = v.x - __uint_as_float(ax & 0xFFFF0000u);
    float ly = v.y - __uint_as_float(ay & 0xFFFF0000u);
    float lz = v.z - __uint_as_float(az & 0xFFFF0000u);
    float lw = v.w - __uint_as_float(aw & 0xFFFF0000u);
    ul.x = pack_bf2(lx, ly);
    ul.y = pack_bf2(lz, lw);
}
__device__ __forceinline__ void split1_fast(float x, __nv_bfloat16& hi, __nv_bfloat16& lo) {
    uint32_t ax = __float_as_uint(x);
    uint32_t h = ax & 0xFFFF0000u;
    uint16_t hbits = (uint16_t)(ax >> 16);
    hi = *(__nv_bfloat16*)&hbits;
    lo = __float2bfloat16_rn(x - __uint_as_float(h));
}

// ---------------------------------------------------------------------------
// Cheap grid barrier: monotonic counter, release-red arrival, acquire poll.
// ---------------------------------------------------------------------------
__device__ __forceinline__ unsigned bar_init()
{
    unsigned c0;
    asm volatile("ld.relaxed.gpu.global.u32 %0, [%1];" : "=r"(c0) : "l"(&g_cnt));
    return (c0 / (unsigned)GRID + 1u) * (unsigned)GRID;
}

__device__ __forceinline__ void bar_arrive()
{
    asm volatile("red.release.gpu.global.add.u32 [%0], 1;" :: "l"(&g_cnt) : "memory");
}
__device__ __forceinline__ void bar_wait(unsigned want)
{
    for (;;) {
        unsigned c;
        asm volatile("ld.acquire.gpu.global.u32 %0, [%1];"
                     : "=r"(c) : "l"(&g_cnt) : "memory");
        if ((int)(c - want) >= 0) break;
        __nanosleep(32);
    }
}

__device__ __forceinline__ void grid_bar(unsigned& want)
{
    __syncthreads();
    if (threadIdx.x == 0) {
        bar_arrive();
        bar_wait(want);
    }
    __syncthreads();
    want += (unsigned)GRID;
}

extern __shared__ float sm[];

#define WKP 1032   // padded k-stride (bf16) for encoder persistent weights
#define HKP 136    // padded k-stride (bf16) for 128-k chunk tiles
#define HSP 68     // float stride for fc scalar tile

// fragment dump: red[kw][n(24)][b(68 pad)]
__device__ __forceinline__ void dump_frag(
    float* red, const float* c0, const float* c1, const float* c2,
    int kw, int mw, int lane)
{
    float* rp = red + kw * 1632;
    int g = lane >> 2, t4 = lane & 3;
    int r0 = mw * 16 + g;
    int n0 = 2 * t4;
    rp[n0 * 68 + r0]            = c0[0];
    rp[(n0 + 1) * 68 + r0]      = c0[1];
    rp[n0 * 68 + r0 + 8]        = c0[2];
    rp[(n0 + 1) * 68 + r0 + 8]  = c0[3];
    rp[(8 + n0) * 68 + r0]           = c1[0];
    rp[(8 + n0 + 1) * 68 + r0]       = c1[1];
    rp[(8 + n0) * 68 + r0 + 8]       = c1[2];
    rp[(8 + n0 + 1) * 68 + r0 + 8]   = c1[3];
    rp[(16 + n0) * 68 + r0]          = c2[0];
    rp[(16 + n0 + 1) * 68 + r0]      = c2[1];
    rp[(16 + n0) * 68 + r0 + 8]      = c2[2];
    rp[(16 + n0 + 1) * 68 + r0 + 8]  = c2[3];
}

// ---------------------------------------------------------------------------
// Tensor-core batched input-gate GEMM (split-bf16, compensated) — R12 version
// ---------------------------------------------------------------------------
#define AKP 40

__global__ void __launch_bounds__(256) tc_gemm(
    const float* __restrict__ X, long sb, long st,
    const float* __restrict__ W, const float* __restrict__ bias,
    float* __restrict__ out, int K)
{
    __shared__ __nv_bfloat16 Ahi[128 * AKP];
    __shared__ __nv_bfloat16 Alo[128 * AKP];
    __shared__ __nv_bfloat16 Bhi[64 * AKP];
    __shared__ __nv_bfloat16 Blo[64 * AKP];

    const int tid  = threadIdx.x;
    const int warp = tid >> 5;
    const int lane = tid & 31;
    const long cb  = (long)blockIdx.x * 64;
    const long rb  = (long)blockIdx.y * 128;

    const int rowA = warp * 16 + ((lane >> 3) & 1) * 8 + (lane & 7);
    const int kA   = ((lane >> 4) & 1) * 8;
    const int lm   = lane & 15;
    const int bRow = lm & 7;
    const int bK   = ((lm >> 3) & 1) * 8;
    const uint32_t AhiA = smem_u32(Ahi);
    const uint32_t AloA = smem_u32(Alo);
    const uint32_t BhiA = smem_u32(Bhi);
    const uint32_t BloA = smem_u32(Blo);

    float acc[8][4];
#pragma unroll
    for (int n = 0; n < 8; n++)
#pragma unroll
        for (int i = 0; i < 4; i++) acc[n][i] = 0.0f;

    for (int k0 = 0; k0 < K; k0 += 32) {
        __syncthreads();
#pragma unroll
        for (int i = 0; i < 4; i++) {
            int idx = (i << 8) + tid;
            int row = idx >> 3, q = idx & 7;
            long r = rb + row;
            long off = (r & 63) * sb + (r >> 6) * st + k0 + (q << 2);
            float4 v = *(const float4*)(X + off);
            uint2 uh, ul;
            split4_fast(v, uh, ul);
            *(uint2*)&Ahi[row * AKP + (q << 2)] = uh;
            *(uint2*)&Alo[row * AKP + (q << 2)] = ul;
        }
#pragma unroll
        for (int i = 0; i < 2; i++) {
            int idx = (i << 8) + tid;
            int row = idx >> 3, q = idx & 7;
            float4 v = *(const float4*)(W + (cb + row) * (long)K + k0 + (q << 2));
            uint2 uh, ul;
            split4_fast(v, uh, ul);
            *(uint2*)&Bhi[row * AKP + (q << 2)] = uh;
            *(uint2*)&Blo[row * AKP + (q << 2)] = ul;
        }
        __syncthreads();

#pragma unroll
        for (int s = 0; s < 2; s++) {
            int kk = s * 16;
            uint32_t ah[4], al[4];
            ldsm4(ah[0], ah[1], ah[2], ah[3],
                  AhiA + (uint32_t)((rowA * AKP + kk + kA) * 2));
            ldsm4(al[0], al[1], al[2], al[3],
                  AloA + (uint32_t)((rowA * AKP + kk + kA) * 2));
#pragma unroll
            for (int nt = 0; nt < 8; nt++) {
                uint32_t bh2[2], bl2[2];
                uint32_t boff = (uint32_t)(((nt * 8 + bRow) * AKP + kk + bK) * 2);
                ldsm2(bh2[0], bh2[1], BhiA + boff);
                ldsm2(bl2[0], bl2[1], BloA + boff);
                mma_bf16(acc[nt], ah, bh2);
                mma_bf16(acc[nt], ah, bl2);
                mma_bf16(acc[nt], al, bh2);
            }
        }
    }

    const int g  = lane >> 2;
    const int t4 = lane & 3;
#pragma unroll
    for (int nt = 0; nt < 8; nt++) {
        long c = cb + nt * 8 + t4 * 2;
        float2 bv = *(const float2*)(bias + c);
        long r0 = rb + warp * 16 + g;
        *(float2*)(out + r0 * G3 + c) = make_float2(acc[nt][0] + bv.x, acc[nt][1] + bv.y);
        *(float2*)(out + (r0 + 8) * G3 + c) = make_float2(acc[nt][2] + bv.x, acc[nt][3] + bv.y);
    }
}

// ---------------------------------------------------------------------------
// Persistent encoder layer — R12 structure, gi staging for t+1 overlapped
// with the grid-barrier wait (arrive -> stage gi -> wait).
// ---------------------------------------------------------------------------
__global__ void __launch_bounds__(NTH, 1) enc_layer_kernel(
    const float* __restrict__ gi,
    const float* __restrict__ Wh,
    const float* __restrict__ bh,
    float* __restrict__ out, long out_t, long out_b)
{
    __nv_bfloat16* whi = (__nv_bfloat16*)sm;
    __nv_bfloat16* wlo = whi + 24 * WKP;
    __nv_bfloat16* hhi = wlo + 24 * WKP;
    __nv_bfloat16* hlo = hhi + 64 * HKP;
    float* red = (float*)(hlo + 64 * HKP);
    float* gis = red + 4 * 24 * 68;

    const int tid  = threadIdx.x;
    const int j0   = blockIdx.x << 3;
    const int warp = tid >> 5;
    const int lane = tid & 31;
    const int mw   = warp & 3;
    const int kw   = warp >> 2;
    const int eb   = tid >> 3;
    const int ej   = tid & 7;
    const int ecol = j0 + ej;

    unsigned want = bar_init();

    for (int i = 0; i < 48; i++) {
        int idx = tid + (i << 9);
        int c = idx >> 10, k = idx & 1023;
        int row = ((c >> 3) << 10) + j0 + (c & 7);
        float w = Wh[(long)row * HID + k];
        __nv_bfloat16 hi, lo;
        split_bf(w, hi, lo);
        whi[c * WKP + k] = hi;
        wlo[c * WKP + k] = lo;
    }
    const float bhr = bh[ecol];
    const float bhz = bh[HID + ecol];
    const float bhn = bh[2 * HID + ecol];

    const int rowA = mw * 16 + ((lane >> 3) & 1) * 8 + (lane & 7);
    const int kA   = ((lane >> 4) & 1) * 8;
    const int lm   = lane & 15;
    const int bOff = (lm & 7) * WKP + ((lm >> 3) & 1) * 8;
    const uint32_t hhiA = smem_u32(hhi);
    const uint32_t hloA = smem_u32(hlo);
    const uint32_t whiA = smem_u32(whi);
    const uint32_t wloA = smem_u32(wlo);

    const int srow = tid >> 3;
    const int sq   = tid & 7;

    // prologue: stage gi tile for t = 0
#pragma unroll
    for (int i = 0; i < 3; i++) {
        int idx = (i << 9) + tid;
        int b = idx / 24;
        int rem = idx - b * 24;
        gis[b * 25 + rem] = gi[(long)b * G3 + ((rem >> 3) << 10) + j0 + (rem & 7)];
    }
    __syncthreads();

    for (int t = 0; t < TSRC; t++) {
        float c0[4], c1[4], c2[4];
#pragma unroll
        for (int i = 0; i < 4; i++) { c0[i] = 0.f; c1[i] = 0.f; c2[i] = 0.f; }

        const float* hprev = out + (long)(t - 1) * out_t;
        float hold = 0.0f;
        float4 rA[2][4];
        if (t > 0) {
            hold = hprev[(long)eb * out_b + ecol];
#pragma unroll
            for (int p = 0; p < 2; p++)
#pragma unroll
                for (int i = 0; i < 4; i++) {
                    int k4 = sq + (i << 3);
                    rA[p][i] = *(const float4*)(hprev + (long)srow * out_b + (p << 7) + (k4 << 2));
                }
        }

        if (t > 0) {
            for (int c = 0; c < 8; c++) {
                __syncthreads();
#pragma unroll
                for (int i = 0; i < 4; i++) {
                    int k4 = sq + (i << 3);
                    uint2 uh, ul;
                    split4_fast(rA[c & 1][i], uh, ul);
                    *(uint2*)&hhi[srow * HKP + (k4 << 2)] = uh;
                    *(uint2*)&hlo[srow * HKP + (k4 << 2)] = ul;
                }
                __syncthreads();
                if (c < 6) {
                    int k0n = (c + 2) << 7;
#pragma unroll
                    for (int i = 0; i < 4; i++) {
                        int k4 = sq + (i << 3);
                        rA[c & 1][i] =
                            *(const float4*)(hprev + (long)srow * out_b + k0n + (k4 << 2));
                    }
                }
                int k0 = c << 7;
#pragma unroll
                for (int s = 0; s < 2; s++) {
                    int kk = kw * 32 + s * 16;
                    int kg = k0 + kk;
                    uint32_t ah[4], al[4];
                    ldsm4(ah[0], ah[1], ah[2], ah[3],
                          hhiA + (uint32_t)((rowA * HKP + kk + kA) * 2));
                    ldsm4(al[0], al[1], al[2], al[3],
                          hloA + (uint32_t)((rowA * HKP + kk + kA) * 2));
                    uint32_t bh2[2], bl2[2];
                    ldsm2(bh2[0], bh2[1], whiA + (uint32_t)((bOff + kg) * 2));
                    ldsm2(bl2[0], bl2[1], wloA + (uint32_t)((bOff + kg) * 2));
                    mma_bf16(c0, ah, bh2); mma_bf16(c0, ah, bl2); mma_bf16(c0, al, bh2);
                    ldsm2(bh2[0], bh2[1], whiA + (uint32_t)((8 * WKP + bOff + kg) * 2));
                    ldsm2(bl2[0], bl2[1], wloA + (uint32_t)((8 * WKP + bOff + kg) * 2));
                    mma_bf16(c1, ah, bh2); mma_bf16(c1, ah, bl2); mma_bf16(c1, al, bh2);
                    ldsm2(bh2[0], bh2[1], whiA + (uint32_t)((16 * WKP + bOff + kg) * 2));
                    ldsm2(bl2[0], bl2[1], wloA + (uint32_t)((16 * WKP + bOff + kg) * 2));
                    mma_bf16(c2, ah, bh2); mma_bf16(c2, ah, bl2); mma_bf16(c2, al, bh2);
                }
            }
        }
        __syncthreads();
        dump_frag(red, c0, c1, c2, kw, mw, lane);
        __syncthreads();

        float s0 = 0.f, s1 = 0.f, s2 = 0.f;
#pragma unroll
        for (int k = 0; k < 4; k++) {
            const float* rp = red + k * 1632 + eb;
            s0 += rp[(ej)      * 68];
            s1 += rp[(8 + ej)  * 68];
            s2 += rp[(16 + ej) * 68];
        }
        const float* gp = gis + eb * 25;
        float GR = gp[ej], GZ = gp[8 + ej], GN = gp[16 + ej];
        float r = sigf(GR + s0 + bhr);
        float z = sigf(GZ + s1 + bhz);
        float n = tanhf(GN + r * (s2 + bhn));
        float hn = (1.0f - z) * n + z * hold;
        out[(long)t * out_t + (long)eb * out_b + ecol] = hn;

        if (t < TSRC - 1) {
            // split barrier: arrive, stage next gi during other blocks' arrival,
            // then wait.
            __syncthreads();                 // all done reading gis/red
            if (tid == 0) bar_arrive();
            {
                const float* gi_t = gi + (long)(t + 1) * BB * G3;
#pragma unroll
                for (int i = 0; i < 3; i++) {
                    int idx = (i << 9) + tid;
                    int b = idx / 24;
                    int rem = idx - b * 24;
                    gis[b * 25 + rem] =
                        gi_t[(long)b * G3 + ((rem >> 3) << 10) + j0 + (rem & 7)];
                }
            }
            if (tid == 0) bar_wait(want);
            __syncthreads();
            want += (unsigned)GRID;
        }
    }
}

// ---------------------------------------------------------------------------
// Decoder tensor phase (R12 version)
// ---------------------------------------------------------------------------
struct TcCtx {
    __nv_bfloat16 *wshi, *wslo, *hhi, *hlo;
    uint32_t wshiA, wsloA, hhiA, hloA;
    int rowA, kA, bOff, kw, tid, j0;
};

__device__ __forceinline__ void tc_phase(
    const float* __restrict__ X, long xs,
    const float* __restrict__ W, int K,
    const TcCtx& cx,
    float (&c0)[4], float (&c1)[4], float (&c2)[4])
{
    const int NC = K >> 7;
    const int srow = cx.tid >> 3;
    const int sq   = cx.tid & 7;
    float4 rx[4];
    float  rw[6];
#pragma unroll
    for (int i = 0; i < 4; i++) {
        int k4 = sq + (i << 3);
        rx[i] = *(const float4*)(X + (long)srow * xs + (k4 << 2));
    }
#pragma unroll
    for (int i = 0; i < 6; i++) {
        int idx = (i << 9) + cx.tid;
        int c = idx >> 7, k = idx & 127;
        int row = ((c >> 3) << 10) + cx.j0 + (c & 7);
        rw[i] = W[(long)row * (long)K + k];
    }
    for (int ci = 0; ci < NC; ci++) {
        __syncthreads();
#pragma unroll
        for (int i = 0; i < 4; i++) {
            int k4 = sq + (i << 3);
            uint2 uh, ul;
            split4_fast(rx[i], uh, ul);
            *(uint2*)&cx.hhi[srow * HKP + (k4 << 2)] = uh;
            *(uint2*)&cx.hlo[srow * HKP + (k4 << 2)] = ul;
        }
#pragma unroll
        for (int i = 0; i < 6; i++) {
            int idx = (i << 9) + cx.tid;
            int c = idx >> 7, k = idx & 127;
            __nv_bfloat16 hi, lo;
            split1_fast(rw[i], hi, lo);
            cx.wshi[c * HKP + k] = hi;
            cx.wslo[c * HKP + k] = lo;
        }
        __syncthreads();
        if (ci + 1 < NC) {
            int k0 = (ci + 1) << 7;
#pragma unroll
            for (int i = 0; i < 4; i++) {
                int k4 = sq + (i << 3);
                rx[i] = *(const float4*)(X + (long)srow * xs + k0 + (k4 << 2));
            }
#pragma unroll
            for (int i = 0; i < 6; i++) {
                int idx = (i << 9) + cx.tid;
                int c = idx >> 7, k = idx & 127;
                int row = ((c >> 3) << 10) + cx.j0 + (c & 7);
                rw[i] = W[(long)row * (long)K + k0 + k];
            }
        }
#pragma unroll
        for (int s = 0; s < 2; s++) {
            int kk = cx.kw * 32 + s * 16;
            uint32_t ah[4], al[4];
            ldsm4(ah[0], ah[1], ah[2], ah[3],
                  cx.hhiA + (uint32_t)((cx.rowA * HKP + kk + cx.kA) * 2));
            ldsm4(al[0], al[1], al[2], al[3],
                  cx.hloA + (uint32_t)((cx.rowA * HKP + kk + cx.kA) * 2));
            uint32_t bh2[2], bl2[2];
            ldsm2(bh2[0], bh2[1], cx.wshiA + (uint32_t)((cx.bOff + kk) * 2));
            ldsm2(bl2[0], bl2[1], cx.wsloA + (uint32_t)((cx.bOff + kk) * 2));
            mma_bf16(c0, ah, bh2); mma_bf16(c0, ah, bl2); mma_bf16(c0, al, bh2);
            ldsm2(bh2[0], bh2[1], cx.wshiA + (uint32_t)((8 * HKP + cx.bOff + kk) * 2));
            ldsm2(bl2[0], bl2[1], cx.wsloA + (uint32_t)((8 * HKP + cx.bOff + kk) * 2));
            mma_bf16(c1, ah, bh2); mma_bf16(c1, ah, bl2); mma_bf16(c1, al, bh2);
            ldsm2(bh2[0], bh2[1], cx.wshiA + (uint32_t)((16 * HKP + cx.bOff + kk) * 2));
            ldsm2(bl2[0], bl2[1], cx.wsloA + (uint32_t)((16 * HKP + cx.bOff + kk) * 2));
            mma_bf16(c2, ah, bh2); mma_bf16(c2, ah, bl2); mma_bf16(c2, al, bh2);
        }
    }
}

#define ZFRAG(c0, c1, c2) \
    do { _Pragma("unroll") for (int i_ = 0; i_ < 4; i_++) { c0[i_]=0.f; c1[i_]=0.f; c2[i_]=0.f; } } while (0)

// ---------------------------------------------------------------------------
// Persistent decoder (R12 version)
// ---------------------------------------------------------------------------
__global__ void __launch_bounds__(NTH, 1) dec_kernel(
    const float* __restrict__ dWi0, const float* __restrict__ dWh0,
    const float* __restrict__ dbi0, const float* __restrict__ dbh0,
    const float* __restrict__ dWi1, const float* __restrict__ dWh1,
    const float* __restrict__ dbi1, const float* __restrict__ dbh1,
    const float* __restrict__ fcW,  const float* __restrict__ fcb,
    const float* __restrict__ enc0_hT,
    const float* __restrict__ enc1_hT,
    float* __restrict__ h0buf, float* __restrict__ h1buf, float* __restrict__ xbuf,
    float* __restrict__ out,
    float* __restrict__ dec_out)
{
    __nv_bfloat16* wshi = (__nv_bfloat16*)sm;
    __nv_bfloat16* wslo = wshi + 24 * HKP;
    __nv_bfloat16* hhi  = wslo + 24 * HKP;
    __nv_bfloat16* hlo  = hhi + 64 * HKP;
    float* redA = (float*)(hlo + 64 * HKP);
    float* redB = redA + 4 * 24 * 68;
    float* fcw  = (float*)sm;
    float* fch  = (float*)hhi;

    const int tid  = threadIdx.x;
    const int j0   = blockIdx.x << 3;
    const int warp = tid >> 5;
    const int lane = tid & 31;
    const int mw   = warp & 3;
    const int kw   = warp >> 2;
    const int eb   = tid >> 3;
    const int ej   = tid & 7;
    const int ecol = j0 + ej;
    const int fb   = tid >> 3;
    const int fcc  = (tid >> 2) & 1;
    const int fks  = tid & 3;
    const int fcol = (blockIdx.x << 1) + fcc;

    TcCtx cx;
    cx.wshi = wshi; cx.wslo = wslo; cx.hhi = hhi; cx.hlo = hlo;
    cx.wshiA = smem_u32(wshi); cx.wsloA = smem_u32(wslo);
    cx.hhiA = smem_u32(hhi);   cx.hloA = smem_u32(hlo);
    cx.rowA = mw * 16 + ((lane >> 3) & 1) * 8 + (lane & 7);
    cx.kA   = ((lane >> 4) & 1) * 8;
    {
        int lm = lane & 15;
        cx.bOff = (lm & 7) * HKP + ((lm >> 3) & 1) * 8;
    }
    cx.kw = kw; cx.tid = tid; cx.j0 = j0;

    unsigned want = bar_init();

    const float b0ir = dbi0[ecol], b0iz = dbi0[HID + ecol], b0in = dbi0[2 * HID + ecol];
    const float b0hr = dbh0[ecol], b0hz = dbh0[HID + ecol], b0hn = dbh0[2 * HID + ecol];
    const float b1ir = dbi1[ecol], b1iz = dbi1[HID + ecol], b1in = dbi1[2 * HID + ecol];
    const float b1hr = dbh1[ecol], b1hz = dbh1[HID + ecol], b1hn = dbh1[2 * HID + ecol];
    const float fcbv = fcb[fcol];

    float c0[4], c1[4], c2[4];

    for (int t = 0; t < TTRG; t++) {
        const int w = t & 1;

        // ================= layer 0 =================
        ZFRAG(c0, c1, c2);
        if (t > 0)
            tc_phase(xbuf, INP, dWi0, INP, cx, c0, c1, c2);
        __syncthreads();
        dump_frag(redA, c0, c1, c2, kw, mw, lane);

        const float* h0p = t ? h0buf + (long)(1 - w) * BB * HID : enc0_hT;
        ZFRAG(c0, c1, c2);
        tc_phase(h0p, HID, dWh0, HID, cx, c0, c1, c2);
        __syncthreads();
        dump_frag(redB, c0, c1, c2, kw, mw, lane);
        __syncthreads();
        {
            float a0 = 0.f, a1 = 0.f, a2 = 0.f, d0 = 0.f, d1 = 0.f, d2 = 0.f;
#pragma unroll
            for (int k = 0; k < 4; k++) {
                const float* ra = redA + k * 1632 + eb;
                const float* rb = redB + k * 1632 + eb;
                a0 += ra[ej * 68];        d0 += rb[ej * 68];
                a1 += ra[(8 + ej) * 68];  d1 += rb[(8 + ej) * 68];
                a2 += ra[(16 + ej) * 68]; d2 += rb[(16 + ej) * 68];
            }
            float hold = h0p[(long)eb * HID + ecol];
            float r = sigf(a0 + b0ir + d0 + b0hr);
            float z = sigf(a1 + b0iz + d1 + b0hz);
            float n = tanhf(a2 + b0in + r * (d2 + b0hn));
            h0buf[(long)w * BB * HID + (long)eb * HID + ecol] = (1.f - z) * n + z * hold;
        }
        grid_bar(want);

        // ================= layer 1 =================
        const float* x1 = h0buf + (long)w * BB * HID;
        ZFRAG(c0, c1, c2);
        tc_phase(x1, HID, dWi1, HID, cx, c0, c1, c2);
        __syncthreads();
        dump_frag(redA, c0, c1, c2, kw, mw, lane);

        const float* h1p = t ? h1buf + (long)(1 - w) * BB * HID : enc1_hT;
        const long   h1s = t ? (long)HID : (long)TSRC * HID;
        ZFRAG(c0, c1, c2);
        tc_phase(h1p, h1s, dWh1, HID, cx, c0, c1, c2);
        __syncthreads();
        dump_frag(redB, c0, c1, c2, kw, mw, lane);
        __syncthreads();
        {
            float a0 = 0.f, a1 = 0.f, a2 = 0.f, d0 = 0.f, d1 = 0.f, d2 = 0.f;
#pragma unroll
            for (int k = 0; k < 4; k++) {
                const float* ra = redA + k * 1632 + eb;
                const float* rb = redB + k * 1632 + eb;
                a0 += ra[ej * 68];        d0 += rb[ej * 68];
                a1 += ra[(8 + ej) * 68];  d1 += rb[(8 + ej) * 68];
                a2 += ra[(16 + ej) * 68]; d2 += rb[(16 + ej) * 68];
            }
            float hold = h1p[(long)eb * h1s + ecol];
            float r = sigf(a0 + b1ir + d0 + b1hr);
            float z = sigf(a1 + b1iz + d1 + b1hz);
            float n = tanhf(a2 + b1in + r * (d2 + b1hn));
            float hn = (1.f - z) * n + z * hold;
            h1buf[(long)w * BB * HID + (long)eb * HID + ecol] = hn;
            dec_out[(long)eb * TTRG * HID + (long)t * HID + ecol] = hn;
        }
        grid_bar(want);

        // ================= fc (scalar, pipelined, overlaid SMEM) ============
        {
            const float* h1c = h1buf + (long)w * BB * HID;
            const int sb = tid >> 3;
            const int sq = tid & 7;
            __syncthreads();
#pragma unroll
            for (int i = 0; i < 4; i++) {
                int idx = (i << 9) + tid;
                int k = idx >> 1, c = idx & 1;
                fcw[idx] = fcW[(long)((blockIdx.x << 1) + c) * HID + k];
            }
            float4 rx[4];
#pragma unroll
            for (int i = 0; i < 4; i++) {
                int k4 = sq + (i << 3);
                rx[i] = *(const float4*)(h1c + (long)sb * HID + (k4 << 2));
            }
            float partial = 0.f;
            for (int ci = 0; ci < 8; ci++) {
                __syncthreads();
#pragma unroll
                for (int i = 0; i < 4; i++) {
                    int k4 = sq + (i << 3);
                    int base = (k4 << 2) * HSP + sb;
                    fch[base]           = rx[i].x;
                    fch[base + HSP]     = rx[i].y;
                    fch[base + 2 * HSP] = rx[i].z;
                    fch[base + 3 * HSP] = rx[i].w;
                }
                __syncthreads();
                if (ci + 1 < 8) {
                    int k0 = (ci + 1) << 7;
#pragma unroll
                    for (int i = 0; i < 4; i++) {
                        int k4 = sq + (i << 3);
                        rx[i] = *(const float4*)(h1c + (long)sb * HID + k0 + (k4 << 2));
                    }
                }
                int k0 = ci << 7;
#pragma unroll 8
                for (int i = 0; i < 32; i++) {
                    int kk = fks * 32 + i;
                    partial += fch[kk * HSP + fb] * fcw[(k0 + kk) * 2 + fcc];
                }
            }
            __syncthreads();
            redA[tid] = partial;
            __syncthreads();
            if (fks == 0) {
                float s = redA[tid] + redA[tid + 1] + redA[tid + 2] + redA[tid + 3] + fcbv;
                out [(long)fb * TTRG * INP + (long)t * INP + fcol] = s;
                xbuf[(long)fb * INP + fcol] = s;
            }
        }
        grid_bar(want);
    }
}

// ---------------------------------------------------------------------------
extern "C" void kernel_launch(void* const* d_in, const int* in_sizes, int n_in,
                              void* d_out, int out_size)
{
    const float* src  = (const float*)d_in[0];
    const float* eWi0 = (const float*)d_in[2];
    const float* eWh0 = (const float*)d_in[3];
    const float* ebi0 = (const float*)d_in[4];
    const float* ebh0 = (const float*)d_in[5];
    const float* eWi1 = (const float*)d_in[6];
    const float* eWh1 = (const float*)d_in[7];
    const float* ebi1 = (const float*)d_in[8];
    const float* ebh1 = (const float*)d_in[9];
    const float* dWi0 = (const float*)d_in[10];
    const float* dWh0 = (const float*)d_in[11];
    const float* dbi0 = (const float*)d_in[12];
    const float* dbh0 = (const float*)d_in[13];
    const float* dWi1 = (const float*)d_in[14];
    const float* dWh1 = (const float*)d_in[15];
    const float* dbi1 = (const float*)d_in[16];
    const float* dbh1 = (const float*)d_in[17];
    const float* fcW  = (const float*)d_in[18];
    const float* fcb  = (const float*)d_in[19];

    float* out     = (float*)d_out;                   // [64, 64, 256]
    float* enc_out = out + (long)BB * TTRG * INP;     // [64, 256, 1024]
    float* dec_out = enc_out + (long)BB * TSRC * HID; // [64, 64, 1024]

    float *gi, *ys0, *h0, *h1, *xbuf;
    cudaGetSymbolAddress((void**)&gi,   g_gi);
    cudaGetSymbolAddress((void**)&ys0,  g_ys0);
    cudaGetSymbolAddress((void**)&h0,   g_h0);
    cudaGetSymbolAddress((void**)&h1,   g_h1);
    cudaGetSymbolAddress((void**)&xbuf, g_x);

    const int ENC_SMEM = 24 * WKP * 2 * 2 + 64 * HKP * 2 * 2
                       + 4 * 24 * 68 * 4 + 64 * 25 * 4;   // 166400 B
    const int DEC_SMEM = (24 * HKP * 2 + 64 * HKP * 2) * 2
                       + 2 * 4 * 24 * 68 * 4;             // 100096 B
    cudaFuncSetAttribute(enc_layer_kernel,
                         cudaFuncAttributeMaxDynamicSharedMemorySize, ENC_SMEM);
    cudaFuncSetAttribute(dec_kernel,
                         cudaFuncAttributeMaxDynamicSharedMemorySize, DEC_SMEM);

    dim3 gridTc(48, 128);

    // ---------- encoder layer 0 ----------
    tc_gemm<<<gridTc, 256>>>(src, 65536L, 256L, eWi0, ebi0, gi, 256);
    enc_layer_kernel<<<GRID, NTH, ENC_SMEM>>>(
        gi, eWh0, ebh0, ys0, (long)BB * HID, (long)HID);

    // ---------- encoder layer 1 ----------
    tc_gemm<<<gridTc, 256>>>(ys0, 1024L, 65536L, eWi1, ebi1, gi, 1024);
    enc_layer_kernel<<<GRID, NTH, ENC_SMEM>>>(
        gi, eWh1, ebh1, enc_out, (long)HID, (long)TSRC * HID);

    // ---------- decoder ----------
    dec_kernel<<<GRID, NTH, DEC_SMEM>>>(
        dWi0, dWh0, dbi0, dbh0,
        dWi1, dWh1, dbi1, dbh1,
        fcW, fcb,
        ys0 + (long)(TSRC - 1) * BB * HID,
        enc_out + (long)(TSRC - 1) * HID,
        h0, h1, xbuf,
        out, dec_out);
}